// round 9
// baseline (speedup 1.0000x reference)
#include <cuda_runtime.h>
#include <math.h>

#define NROWS 500000
#define NA 5
#define TT 8
#define NE 18
#define MB 4
#define EPSV 1e-8f
#define ML2 (0.02f * 0.02f)
#define BLK 128
#define NCLS (NE * MB * TT)   // 576

__global__ void zero_out_kernel(float* out) { out[0] = 0.0f; }

__device__ __forceinline__ float sqrt_approx(float a) {
    float r; asm("sqrt.approx.f32 %0, %1;" : "=f"(r) : "f"(a)); return r;
}
__device__ __forceinline__ float rcp_approx(float a) {
    float r; asm("rcp.approx.f32 %0, %1;" : "=f"(r) : "f"(a)); return r;
}

// 5-way predicated select (ISETP + SEL, no branches, no local memory)
__device__ __forceinline__ float2 sel5(int i, float2 a0, float2 a1, float2 a2,
                                       float2 a3, float2 a4) {
    float2 r = a0;
    r.x = (i == 1) ? a1.x : r.x;  r.y = (i == 1) ? a1.y : r.y;
    r.x = (i == 2) ? a2.x : r.x;  r.y = (i == 2) ? a2.y : r.y;
    r.x = (i == 3) ? a3.x : r.x;  r.y = (i == 3) ? a3.y : r.y;
    r.x = (i == 4) ? a4.x : r.x;  r.y = (i == 4) ? a4.y : r.y;
    return r;
}

__global__ void __launch_bounds__(BLK, 8) loss_kernel(
    const float* __restrict__ x,
    const float* __restrict__ yt,
    const float* __restrict__ yp,
    const float* __restrict__ mk,
    const int* __restrict__ trip,
    const int* __restrict__ tvalid,
    float* __restrict__ out)
{
    __shared__ __align__(16) unsigned s_pk[NCLS];    // 2.3 KB
    __shared__ __align__(16) float2  s_tp[BLK * 15]; // interleaved {t,p}: 15 KB
    __shared__ __align__(16) float   s_m[BLK * 15];  // mask staged: 7.5 KB
    __shared__ float warpsum[BLK / 32];

    const int tid  = threadIdx.x;
    const int row0 = blockIdx.x * BLK;
    const int cnt  = min(BLK, NROWS - row0);
    const bool live = (tid < cnt);
    const int row  = row0 + tid;

    // early gate/bead load (only strided LDG left; 1 LDG.64/thread)
    float gate = 0.0f, bd = 0.0f;
    if (live) {
        const float2 xg = *(const float2*)(x + (size_t)row * 38 + 36);
        bd = xg.x; gate = xg.y;
    }

    // -------- pack tables --------
    for (int e = tid; e < NCLS; e += BLK) {
        const int i0 = trip[3 * e + 0];
        const int i1 = trip[3 * e + 1];
        const int i2 = trip[3 * e + 2];
        const int v  = tvalid[e];
        const unsigned ok = (i0 >= 0 && i1 >= 0 && i2 >= 0 && v > 0) ? 1u : 0u;
        const unsigned ii = (unsigned)max(i0, 0);
        const unsigned jj = (unsigned)max(i1, 0);
        const unsigned kk = (unsigned)max(i2, 0);
        s_pk[e] = ii | (jj << 4) | (kk << 8) | (ok << 12);
    }

    // -------- coalesced staging: t/p interleaved + mask --------
    if (cnt == BLK) {
        const float2* gt2 = (const float2*)(yt + (size_t)row0 * 15);
        const float2* gp2 = (const float2*)(yp + (size_t)row0 * 15);
        const float4* gm4 = (const float4*)(mk + (size_t)row0 * 15);
        float4* d4 = (float4*)s_tp;
        float4* m4 = (float4*)s_m;
#pragma unroll
        for (int k = 0; k < 8; k++) {
            int i = tid + k * BLK;
            if (i < 960) {
                float2 a = gt2[i];
                float2 b = gp2[i];
                d4[i] = make_float4(a.x, b.x, a.y, b.y);
            }
            if (i < 480) m4[i] = gm4[i];
        }
    } else {
        const int tot = cnt * 15;
        const float* gt = yt + (size_t)row0 * 15;
        const float* gp = yp + (size_t)row0 * 15;
        const float* gm = mk + (size_t)row0 * 15;
        for (int i = tid; i < tot; i += BLK) {
            s_tp[i] = make_float2(gt[i], gp[i]);
            s_m[i] = gm[i];
        }
    }
    __syncthreads();

    float acc = 0.0f;

    if (live) {
        const float2* tp = s_tp + tid * 15;  // 120B lane stride: conflict-free
        const float*  mr = s_m  + tid * 15;  // 60B lane stride: conflict-free

        // mask bits (15 conflict-free LDS.32)
        unsigned mb = 0;
#pragma unroll
        for (int e = 0; e < 15; e++)
            mb |= (mr[e] > 0.0f ? 1u : 0u) << e;

        // ---- load all 5 atoms {t,p} into NAMED registers (15 LDS.64, once) ----
        float2 q00 = tp[0],  q01 = tp[1],  q02 = tp[2];
        float2 q10 = tp[3],  q11 = tp[4],  q12 = tp[5];
        float2 q20 = tp[6],  q21 = tp[7],  q22 = tp[8];
        float2 q30 = tp[9],  q31 = tp[10], q32 = tp[11];
        float2 q40 = tp[12], q41 = tp[13], q42 = tp[14];

        // ---------------- atom MSE ----------------
        unsigned avmask = 0;
        float num = 0.0f;
        {
            float d;
            unsigned g;
            g = mb & 7u;
            d = q00.x - q00.y; num += (g & 1u) ? d * d : 0.0f;
            d = q01.x - q01.y; num += (g & 2u) ? d * d : 0.0f;
            d = q02.x - q02.y; num += (g & 4u) ? d * d : 0.0f;
            avmask |= (g ? 1u : 0u);
            g = (mb >> 3) & 7u;
            d = q10.x - q10.y; num += (g & 1u) ? d * d : 0.0f;
            d = q11.x - q11.y; num += (g & 2u) ? d * d : 0.0f;
            d = q12.x - q12.y; num += (g & 4u) ? d * d : 0.0f;
            avmask |= (g ? 1u : 0u) << 1;
            g = (mb >> 6) & 7u;
            d = q20.x - q20.y; num += (g & 1u) ? d * d : 0.0f;
            d = q21.x - q21.y; num += (g & 2u) ? d * d : 0.0f;
            d = q22.x - q22.y; num += (g & 4u) ? d * d : 0.0f;
            avmask |= (g ? 1u : 0u) << 2;
            g = (mb >> 9) & 7u;
            d = q30.x - q30.y; num += (g & 1u) ? d * d : 0.0f;
            d = q31.x - q31.y; num += (g & 2u) ? d * d : 0.0f;
            d = q32.x - q32.y; num += (g & 4u) ? d * d : 0.0f;
            avmask |= (g ? 1u : 0u) << 3;
            g = (mb >> 12) & 7u;
            d = q40.x - q40.y; num += (g & 1u) ? d * d : 0.0f;
            d = q41.x - q41.y; num += (g & 2u) ? d * d : 0.0f;
            d = q42.x - q42.y; num += (g & 4u) ? d * d : 0.0f;
            avmask |= (g ? 1u : 0u) << 4;
        }
        float atom = num * rcp_approx((float)__popc(avmask) + EPSV);

        // ---------------- angle loss ----------------
        if (!isfinite(gate)) gate = 0.0f;
        int rid = (int)rintf(gate) - 1;
        rid = min(max(rid, 0), NE - 1);
        if (!isfinite(bd)) bd = 0.0f;
        int bid = min(max((int)rintf(bd), 0), MB - 1);

        const int base = (rid * MB + bid) * TT;      // multiple of 8 -> 32B aligned
        const uint4* pkp = (const uint4*)(s_pk + base);

        const float lo = -1.0f + 1e-6f, hi = 1.0f - 1e-6f;
        float anum = 0.0f, aden = 0.0f;

#pragma unroll
        for (int h = 0; h < 2; h++) {
            const uint4 pk4 = pkp[h];
            const unsigned pkw[4] = { pk4.x, pk4.y, pk4.z, pk4.w };
#pragma unroll
            for (int e = 0; e < 4; e++) {
                const unsigned pk = pkw[e];
                const int ii = pk & 15;
                const int jj = (pk >> 4) & 15;
                const int kk = (pk >> 8) & 15;
                unsigned okb = (pk >> 12) & (avmask >> ii) & (avmask >> jj) & (avmask >> kk) & 1u;

                // register gather: no shared-memory access in this loop
                float2 jx = sel5(jj, q00, q10, q20, q30, q40);
                float2 jy = sel5(jj, q01, q11, q21, q31, q41);
                float2 jz = sel5(jj, q02, q12, q22, q32, q42);
                float2 ix = sel5(ii, q00, q10, q20, q30, q40);
                float2 iy = sel5(ii, q01, q11, q21, q31, q41);
                float2 iz = sel5(ii, q02, q12, q22, q32, q42);
                float2 kx = sel5(kk, q00, q10, q20, q30, q40);
                float2 ky = sel5(kk, q01, q11, q21, q31, q41);
                float2 kz = sel5(kk, q02, q12, q22, q32, q42);

                // ---- true side (.x) ----
                float a1x = ix.x - jx.x, a1y = iy.x - jy.x, a1z = iz.x - jz.x;
                float a2x = kx.x - jx.x, a2y = ky.x - jy.x, a2z = kz.x - jz.x;
                float l1t = a1x * a1x + a1y * a1y + a1z * a1z;
                float l2t = a2x * a2x + a2y * a2y + a2z * a2z;
                float ddt = a1x * a2x + a1y * a2y + a1z * a2z;
                float ct = ddt * rsqrtf(fmaxf(l1t, ML2) * fmaxf(l2t, ML2));
                float sint = sqrt_approx(fmaxf(1.0f - ct * ct, 0.0f));
                ct = fminf(fmaxf(ct, lo), hi);

                // ---- pred side (.y) ----
                float b1x = ix.y - jx.y, b1y = iy.y - jy.y, b1z = iz.y - jz.y;
                float b2x = kx.y - jx.y, b2y = ky.y - jy.y, b2z = kz.y - jz.y;
                float l1p = b1x * b1x + b1y * b1y + b1z * b1z;
                float l2p = b2x * b2x + b2y * b2y + b2z * b2z;
                float ddp = b1x * b2x + b1y * b2y + b1z * b2z;
                float cp = ddp * rsqrtf(fmaxf(l1p, ML2) * fmaxf(l2p, ML2));
                float sinp = sqrt_approx(fmaxf(1.0f - cp * cp, 0.0f));
                cp = fminf(fmaxf(cp, lo), hi);

                bool ok = okb && (l1t > ML2) && (l2t > ML2) && (l1p > ML2) && (l2p > ML2);

                float dc = cp - ct;
                float ds = sinp - sint;
                if (ok) { anum += dc * dc + ds * ds; aden += 1.0f; }
            }
        }
        float ang = anum * rcp_approx(aden + EPSV);

        acc = atom + ang;
    }

    // ---------------- block reduction ----------------
#pragma unroll
    for (int off = 16; off > 0; off >>= 1)
        acc += __shfl_down_sync(0xffffffffu, acc, off);

    if ((tid & 31) == 0) warpsum[tid >> 5] = acc;
    __syncthreads();
    if (tid == 0) {
        float s = 0.0f;
#pragma unroll
        for (int w = 0; w < BLK / 32; w++) s += warpsum[w];
        atomicAdd(out, s * (1.0f / (float)NROWS));
    }
}

extern "C" void kernel_launch(void* const* d_in, const int* in_sizes, int n_in,
                              void* d_out, int out_size)
{
    const float* x      = (const float*)d_in[0];
    const float* yt     = (const float*)d_in[1];
    const float* yp     = (const float*)d_in[2];
    const float* mk     = (const float*)d_in[3];
    const int*   trip   = (const int*)d_in[4];
    const int*   tvalid = (const int*)d_in[5];
    float* out = (float*)d_out;

    zero_out_kernel<<<1, 1>>>(out);
    const int grid = (NROWS + BLK - 1) / BLK;
    loss_kernel<<<grid, BLK>>>(x, yt, yp, mk, trip, tvalid, out);
}

// round 10
// speedup vs baseline: 1.2051x; 1.2051x over previous
#include <cuda_runtime.h>
#include <math.h>

#define NROWS 500000
#define NA 5
#define TT 8
#define NE 18
#define MB 4
#define EPSV 1e-8f
#define ML2 (0.02f * 0.02f)
#define BLK 128
#define NCLS (NE * MB * TT)   // 576

__global__ void zero_out_kernel(float* out) { out[0] = 0.0f; }

__device__ __forceinline__ float sqrt_approx(float a) {
    float r; asm("sqrt.approx.f32 %0, %1;" : "=f"(r) : "f"(a)); return r;
}
__device__ __forceinline__ float rcp_approx(float a) {
    float r; asm("rcp.approx.f32 %0, %1;" : "=f"(r) : "f"(a)); return r;
}

__global__ void __launch_bounds__(BLK, 9) loss_kernel(
    const float* __restrict__ x,
    const float* __restrict__ yt,
    const float* __restrict__ yp,
    const float* __restrict__ mk,
    const int* __restrict__ trip,
    const int* __restrict__ tvalid,
    float* __restrict__ out)
{
    __shared__ __align__(16) unsigned s_pk[NCLS];    // 2.3 KB
    __shared__ __align__(16) float2  s_tp[BLK * 15]; // interleaved {t,p}: 15 KB
    __shared__ __align__(16) float   s_m[BLK * 15];  // mask staged: 7.5 KB
    __shared__ float warpsum[BLK / 32];

    const int tid  = threadIdx.x;
    const int row0 = blockIdx.x * BLK;
    const int cnt  = min(BLK, NROWS - row0);
    const bool live = (tid < cnt);
    const int row  = row0 + tid;

    // early gate/bead load (only strided LDG left; 1 LDG.64/thread)
    float gate = 0.0f, bd = 0.0f;
    if (live) {
        const float2 xg = *(const float2*)(x + (size_t)row * 38 + 36);
        bd = xg.x; gate = xg.y;
    }

    // -------- pack tables --------
    for (int e = tid; e < NCLS; e += BLK) {
        const int i0 = trip[3 * e + 0];
        const int i1 = trip[3 * e + 1];
        const int i2 = trip[3 * e + 2];
        const int v  = tvalid[e];
        const unsigned ok = (i0 >= 0 && i1 >= 0 && i2 >= 0 && v > 0) ? 1u : 0u;
        const unsigned ii = (unsigned)max(i0, 0);
        const unsigned jj = (unsigned)max(i1, 0);
        const unsigned kk = (unsigned)max(i2, 0);
        s_pk[e] = ii | (jj << 4) | (kk << 8) | (ok << 12);
    }

    // -------- coalesced staging: t/p interleaved + mask --------
    if (cnt == BLK) {
        const float2* gt2 = (const float2*)(yt + (size_t)row0 * 15);
        const float2* gp2 = (const float2*)(yp + (size_t)row0 * 15);
        const float4* gm4 = (const float4*)(mk + (size_t)row0 * 15);
        float4* d4 = (float4*)s_tp;
        float4* m4 = (float4*)s_m;
#pragma unroll
        for (int k = 0; k < 8; k++) {
            int i = tid + k * BLK;
            if (i < 960) {
                float2 a = gt2[i];
                float2 b = gp2[i];
                d4[i] = make_float4(a.x, b.x, a.y, b.y);  // s_tp[2i], s_tp[2i+1]
            }
            if (i < 480) m4[i] = gm4[i];
        }
    } else {
        const int tot = cnt * 15;
        const float* gt = yt + (size_t)row0 * 15;
        const float* gp = yp + (size_t)row0 * 15;
        const float* gm = mk + (size_t)row0 * 15;
        for (int i = tid; i < tot; i += BLK) {
            s_tp[i] = make_float2(gt[i], gp[i]);
            s_m[i] = gm[i];
        }
    }
    __syncthreads();

    float acc = 0.0f;

    if (live) {
        const float2* tp = s_tp + tid * 15;  // 120B lane stride: conflict-free per phase
        const float*  mr = s_m  + tid * 15;  // 60B lane stride: conflict-free

        // mask bits (15 conflict-free LDS.32 replacing 15 strided LDG.32)
        unsigned mb = 0;
#pragma unroll
        for (int e = 0; e < 15; e++)
            mb |= (mr[e] > 0.0f ? 1u : 0u) << e;

        // ---------------- atom MSE ----------------
        unsigned avmask = 0;
        float num = 0.0f;
#pragma unroll
        for (int a = 0; a < NA; a++) {
            float2 q0 = tp[3 * a + 0];
            float2 q1 = tp[3 * a + 1];
            float2 q2 = tp[3 * a + 2];
            float d0 = q0.x - q0.y, d1 = q1.x - q1.y, d2 = q2.x - q2.y;
            unsigned g = (mb >> (3 * a)) & 7u;
            num += ((g & 1u) ? d0 * d0 : 0.0f)
                 + ((g & 2u) ? d1 * d1 : 0.0f)
                 + ((g & 4u) ? d2 * d2 : 0.0f);
            avmask |= (g ? 1u : 0u) << a;
        }
        float atom = num * rcp_approx((float)__popc(avmask) + EPSV);

        // ---------------- angle loss ----------------
        if (!isfinite(gate)) gate = 0.0f;
        int rid = (int)rintf(gate) - 1;
        rid = min(max(rid, 0), NE - 1);
        if (!isfinite(bd)) bd = 0.0f;
        int bid = min(max((int)rintf(bd), 0), MB - 1);

        const int base = (rid * MB + bid) * TT;      // multiple of 8 -> 32B aligned
        const uint4* pkp = (const uint4*)(s_pk + base);

        const float lo = -1.0f + 1e-6f, hi = 1.0f - 1e-6f;
        float anum = 0.0f, aden = 0.0f;

#pragma unroll
        for (int h = 0; h < 2; h++) {
            const uint4 pk4 = pkp[h];
            const unsigned pkw[4] = { pk4.x, pk4.y, pk4.z, pk4.w };
#pragma unroll
            for (int e = 0; e < 4; e++) {
                const unsigned pk = pkw[e];
                const int ii = pk & 15;
                const int jj = (pk >> 4) & 15;
                const int kk = (pk >> 8) & 15;
                unsigned okb = (pk >> 12) & (avmask >> ii) & (avmask >> jj) & (avmask >> kk) & 1u;

                // one LDS.64 per component serves BOTH true (.x) and pred (.y)
                float2 j0 = tp[jj * 3 + 0], j1 = tp[jj * 3 + 1], j2 = tp[jj * 3 + 2];
                float2 i0 = tp[ii * 3 + 0], i1 = tp[ii * 3 + 1], i2 = tp[ii * 3 + 2];
                float2 k0 = tp[kk * 3 + 0], k1 = tp[kk * 3 + 1], k2 = tp[kk * 3 + 2];

                // ---- true side (.x) ----
                float a1x = i0.x - j0.x, a1y = i1.x - j1.x, a1z = i2.x - j2.x;
                float a2x = k0.x - j0.x, a2y = k1.x - j1.x, a2z = k2.x - j2.x;
                float l1t = a1x * a1x + a1y * a1y + a1z * a1z;
                float l2t = a2x * a2x + a2y * a2y + a2z * a2z;
                float ddt = a1x * a2x + a1y * a2y + a1z * a2z;
                float ct = ddt * rsqrtf(fmaxf(l1t, ML2) * fmaxf(l2t, ML2));
                float sint = sqrt_approx(fmaxf(1.0f - ct * ct, 0.0f));
                ct = fminf(fmaxf(ct, lo), hi);

                // ---- pred side (.y) ----
                float b1x = i0.y - j0.y, b1y = i1.y - j1.y, b1z = i2.y - j2.y;
                float b2x = k0.y - j0.y, b2y = k1.y - j1.y, b2z = k2.y - j2.y;
                float l1p = b1x * b1x + b1y * b1y + b1z * b1z;
                float l2p = b2x * b2x + b2y * b2y + b2z * b2z;
                float ddp = b1x * b2x + b1y * b2y + b1z * b2z;
                float cp = ddp * rsqrtf(fmaxf(l1p, ML2) * fmaxf(l2p, ML2));
                float sinp = sqrt_approx(fmaxf(1.0f - cp * cp, 0.0f));
                cp = fminf(fmaxf(cp, lo), hi);

                bool ok = okb && (l1t > ML2) && (l2t > ML2) && (l1p > ML2) && (l2p > ML2);

                float dc = cp - ct;
                float ds = sinp - sint;
                if (ok) { anum += dc * dc + ds * ds; aden += 1.0f; }
            }
        }
        float ang = anum * rcp_approx(aden + EPSV);

        acc = atom + ang;
    }

    // ---------------- block reduction ----------------
#pragma unroll
    for (int off = 16; off > 0; off >>= 1)
        acc += __shfl_down_sync(0xffffffffu, acc, off);

    if ((tid & 31) == 0) warpsum[tid >> 5] = acc;
    __syncthreads();
    if (tid == 0) {
        float s = 0.0f;
#pragma unroll
        for (int w = 0; w < BLK / 32; w++) s += warpsum[w];
        atomicAdd(out, s * (1.0f / (float)NROWS));
    }
}

extern "C" void kernel_launch(void* const* d_in, const int* in_sizes, int n_in,
                              void* d_out, int out_size)
{
    const float* x      = (const float*)d_in[0];
    const float* yt     = (const float*)d_in[1];
    const float* yp     = (const float*)d_in[2];
    const float* mk     = (const float*)d_in[3];
    const int*   trip   = (const int*)d_in[4];
    const int*   tvalid = (const int*)d_in[5];
    float* out = (float*)d_out;

    zero_out_kernel<<<1, 1>>>(out);
    const int grid = (NROWS + BLK - 1) / BLK;
    loss_kernel<<<grid, BLK>>>(x, yt, yp, mk, trip, tvalid, out);
}